// round 12
// baseline (speedup 1.0000x reference)
#include <cuda_runtime.h>
#include <cstdint>

// HolographicFMLayer: batched all-pairs circular convolution.
// inputs: float32 [B, 24, 64]  ->  out: float32 [B, 276, 64]
// out[b,p,n] = sum_k x[b,i,k] * x[b,j,(n-k) mod 64], pairs = triu_indices(24, k=1)
//
// CRT split: x^64-1 = (x^16-1)(x^16+1)(x^32+1)
//   per field: u = lo+hi, v = (lo-hi)/sqrt2; P=(u_lo+u_hi)/2, Q=(u_lo-u_hi)/2
//   per pair : d1 = cyclic16(P), d2 = negacyclic16(Q), c2 = negacyclic32(v)
//   recon    : c1[n<16]=d1+d2, c1[16..31]=d1-d2; out[n<32]=c1+c2, out[n+32]=c1-c2
// 1536 FMA/pair (vs 4096 direct). 2 threads/pair (role = lane parity).
//
// R11: KILL THE WARP DIVERGENCE. Since R3, phase 2 branched per-role into two
// separate fully-unrolled conv32 bodies; roles are interleaved lanes, so every
// warp serially executed BOTH ~590-instr bodies half-masked (issue forensics:
// ~1650 issues/warp == conv16 + 2x conv32 + overhead, exactly). QOFF is only
// an additive offset into B, so fold it into the base pointer and use ONE
// conv32 instantiation. Scalar sliding-window engine (R1-proven).

#define NF 24
#define NPAIR 276
#define LEN 64
#define THREADS 192
#define PAIRS_PER_BLOCK 92      // 3 blocks per batch
#define ACTIVE (PAIRS_PER_BLOCK * 2)
#define SV 65                   // 64-entry rows: 65 mod 32 == 1
#define SP 33                   // 32-entry rows: 33 mod 32 == 1
#define OFF_P (NF * SV)                 // 1560
#define OFF_Q (OFF_P + NF * SP + 24)    // +24 pad: (OFF_Q-OFF_P) mod 32 == 16
#define SMEM_FLOATS (OFF_Q + NF * SP)

// constexpr-built triu pair table in constant memory
struct PairTab { unsigned short ij[NPAIR]; };  // i*32 + j
static constexpr PairTab make_tab() {
    PairTab t{};
    int p = 0;
    for (int i = 0; i < NF; ++i)
        for (int j = i + 1; j < NF; ++j) { t.ij[p] = (unsigned short)(i * 32 + j); ++p; }
    return t;
}
__constant__ PairTab TAB = make_tab();

// Length-N convolution, 16 consecutive outputs starting at the (pointer-folded)
// offset of B:  acc[q] = sum_{k=0}^{N-1} A[k+N] * B[q-k+N]
// Scalar sliding window: at iter k, w[q] = B[q+N-k]; shifts rename for free.
template <int N>
__device__ __forceinline__ void conv16s(const float* __restrict__ A,
                                        const float* __restrict__ B,
                                        float* __restrict__ acc)
{
    float w[16];
#pragma unroll
    for (int q = 0; q < 16; ++q) w[q] = B[q + N];

    // k = 0 peeled as mul (no acc zero-init)
    {
        const float a = A[N];
#pragma unroll
        for (int q = 0; q < 16; ++q) acc[q] = a * w[q];
        const float nw = B[N - 1];
#pragma unroll
        for (int q = 15; q > 0; --q) w[q] = w[q - 1];
        w[0] = nw;
    }
#pragma unroll
    for (int k = 1; k < N; ++k) {
        const float a = A[N + k];
#pragma unroll
        for (int q = 0; q < 16; ++q) acc[q] = fmaf(a, w[q], acc[q]);
        const float nw = B[N - 1 - k];   // k==N-1 value unused; still in-bounds
#pragma unroll
        for (int q = 15; q > 0; --q) w[q] = w[q - 1];
        w[0] = nw;
    }
}

__global__ __launch_bounds__(THREADS, 6)
void holo_nodiv_kernel(const float* __restrict__ in, float* __restrict__ out)
{
    __shared__ float smem[SMEM_FLOATS];
    float* __restrict__ bufV = smem;           // negacyclic-32 operand, scale 1/sqrt2
    float* __restrict__ bufP = smem + OFF_P;   // cyclic-16 operand (dup), scale 1/2
    float* __restrict__ bufQ = smem + OFF_Q;   // negacyclic-16 operand, scale 1/2

    const int batch = blockIdx.x;
    const float* __restrict__ src = in + (size_t)batch * (NF * LEN);
    const int tid = threadIdx.x;

    // ---- per-field folds ----
    for (int idx = tid; idx < NF * 16; idx += THREADS) {
        const int f = idx >> 4, m = idx & 15;
        const float* x = src + f * LEN;
        const float x0 = x[m], x1 = x[m + 16], x2 = x[m + 32], x3 = x[m + 48];
        const float s = 0.70710678118654752f;
        const float vlo = (x0 - x2) * s, vhi = (x1 - x3) * s;
        const float ulo = x0 + x2,       uhi = x1 + x3;
        const float P = (ulo + uhi) * 0.5f, Q = (ulo - uhi) * 0.5f;
        float* bV = bufV + f * SV;
        bV[m]      = -vlo;  bV[m + 16] = -vhi;
        bV[m + 32] =  vlo;  bV[m + 48] =  vhi;
        float* bP = bufP + f * SP;
        bP[m] = P;  bP[m + 16] = P;
        float* bQ = bufQ + f * SP;
        bQ[m] = -Q; bQ[m + 16] = Q;
    }
    __syncthreads();

    const int role = tid & 1;                          // lanes 2p, 2p+1 share a pair
    int p = blockIdx.y * PAIRS_PER_BLOCK + (tid >> 1);
    const bool live = (tid < ACTIVE);
    if (p >= NPAIR) p = NPAIR - 1;                     // tail threads duplicate, no store
    const int ij = TAB.ij[p];
    const int i  = ij >> 5;
    const int j  = ij & 31;

    // ---- phase 1: one 16-conv each (role0: cyclic P, role1: negacyclic Q) ----
    // Pointer select only — single code path, no divergence.
    const float* A16 = (role ? bufQ : bufP) + i * SP;
    const float* B16 = (role ? bufQ : bufP) + j * SP;
    float d[16];
    conv16s<16>(A16, B16, d);                          // d[q] = d_role[q]

    // exchange between role threads (adjacent lanes), fold into c1
    // role0: c1[n] = d1+d2 (n = q);  role1: c1[n] = d1-d2 (n = 16+q)
    float c1[16];
#pragma unroll
    for (int q = 0; q < 16; ++q) {
        const float other = __shfl_xor_sync(0xFFFFFFFFu, d[q], 1);
        c1[q] = role ? (other - d[q]) : (d[q] + other);
    }

    // ---- phase 2: negacyclic-32, 16 outputs per role ----
    // QOFF = role*16 folded into the B base pointer -> ONE instantiation.
    // role lanes read banks j and j+16: disjoint halves, conflict-free.
    const float* A32 = bufV + i * SV;
    const float* B32 = bufV + j * SV + (role << 4);
    float av[16];
    conv16s<32>(A32, B32, av);                         // av[q] = c2[16*role + q]

    // ---- reconstruct & store ----
    if (live) {
        const int base = role << 4;  // 0 or 16
        float4* __restrict__ dst =
            (float4*)(out + ((size_t)batch * NPAIR + p) * LEN + base);
#pragma unroll
        for (int g = 0; g < 4; ++g) {
            dst[g] = make_float4(c1[4*g+0] + av[4*g+0], c1[4*g+1] + av[4*g+1],
                                 c1[4*g+2] + av[4*g+2], c1[4*g+3] + av[4*g+3]);
            dst[g + 8] = make_float4(c1[4*g+0] - av[4*g+0], c1[4*g+1] - av[4*g+1],
                                     c1[4*g+2] - av[4*g+2], c1[4*g+3] - av[4*g+3]);
        }
    }
}

extern "C" void kernel_launch(void* const* d_in, const int* in_sizes, int n_in,
                              void* d_out, int out_size)
{
    const float* in  = (const float*)d_in[0];
    float*       out = (float*)d_out;
    const int batches = in_sizes[0] / (NF * LEN);   // 2048 for the bench shape
    dim3 grid(batches, 3);
    holo_nodiv_kernel<<<grid, THREADS>>>(in, out);
}

// round 14
// speedup vs baseline: 2.2536x; 2.2536x over previous
#include <cuda_runtime.h>
#include <cstdint>

// HolographicFMLayer: batched all-pairs circular convolution.
// inputs: float32 [B, 24, 64]  ->  out: float32 [B, 276, 64]
// out[b,p,n] = sum_k x[b,i,k] * x[b,j,(n-k) mod 64], pairs = triu_indices(24, k=1)
//
// CRT split: x^64-1 = (x^16-1)(x^16+1)(x^32+1)
//   per field: u = lo+hi, v = (lo-hi)/sqrt2; P=(u_lo+u_hi)/2, Q=(u_lo-u_hi)/2
//   per pair : d1 = cyclic16(P), d2 = negacyclic16(Q), c2 = negacyclic32(v)
//   recon    : c1[n<16]=d1+d2, c1[16..31]=d1-d2; out[n<32]=c1+c2, out[n+32]=c1-c2
// 1536 FMA/pair (vs 4096 direct). 2 threads/pair (role = lane parity).
//
// R11 removed the per-role divergent conv32 duplication (correct) but kept the
// 56-reg cap; the merged single path's ~60-float live set spilled to local
// (DRAM 59.8%, 151us). R12: same no-divergence structure with an 85-reg cap
// (launch_bounds(192,4)), conv32-first ordering, and fused exchange/recon so
// c1 is never materialized. Spills gone -> honestly FMA-pipe-bound.

#define NF 24
#define NPAIR 276
#define LEN 64
#define THREADS 192
#define PAIRS_PER_BLOCK 92      // 3 blocks per batch
#define ACTIVE (PAIRS_PER_BLOCK * 2)
#define SV 65                   // 64-entry rows: 65 mod 32 == 1
#define SP 33                   // 32-entry rows: 33 mod 32 == 1
#define OFF_P (NF * SV)                 // 1560
#define OFF_Q (OFF_P + NF * SP + 24)    // +24 pad: (OFF_Q-OFF_P) mod 32 == 16
#define SMEM_FLOATS (OFF_Q + NF * SP)

// constexpr-built triu pair table in constant memory
struct PairTab { unsigned short ij[NPAIR]; };  // i*32 + j
static constexpr PairTab make_tab() {
    PairTab t{};
    int p = 0;
    for (int i = 0; i < NF; ++i)
        for (int j = i + 1; j < NF; ++j) { t.ij[p] = (unsigned short)(i * 32 + j); ++p; }
    return t;
}
__constant__ PairTab TAB = make_tab();

// Length-N convolution, 16 consecutive outputs (offset pre-folded into B):
//   acc[q] = sum_{k=0}^{N-1} A[k+N] * B[q-k+N]
// Scalar sliding window; shifts rename to zero instructions when unspilled.
template <int N>
__device__ __forceinline__ void conv16s(const float* __restrict__ A,
                                        const float* __restrict__ B,
                                        float* __restrict__ acc)
{
    float w[16];
#pragma unroll
    for (int q = 0; q < 16; ++q) w[q] = B[q + N];

    // k = 0 peeled as mul (no acc zero-init)
    {
        const float a = A[N];
#pragma unroll
        for (int q = 0; q < 16; ++q) acc[q] = a * w[q];
        const float nw = B[N - 1];
#pragma unroll
        for (int q = 15; q > 0; --q) w[q] = w[q - 1];
        w[0] = nw;
    }
#pragma unroll
    for (int k = 1; k < N; ++k) {
        const float a = A[N + k];
#pragma unroll
        for (int q = 0; q < 16; ++q) acc[q] = fmaf(a, w[q], acc[q]);
        const float nw = B[N - 1 - k];   // k==N-1 value unused; still in-bounds
#pragma unroll
        for (int q = 15; q > 0; --q) w[q] = w[q - 1];
        w[0] = nw;
    }
}

__global__ __launch_bounds__(THREADS, 4)
void holo_r12_kernel(const float* __restrict__ in, float* __restrict__ out)
{
    __shared__ float smem[SMEM_FLOATS];
    float* __restrict__ bufV = smem;           // negacyclic-32 operand, scale 1/sqrt2
    float* __restrict__ bufP = smem + OFF_P;   // cyclic-16 operand (dup), scale 1/2
    float* __restrict__ bufQ = smem + OFF_Q;   // negacyclic-16 operand, scale 1/2

    const int batch = blockIdx.x;
    const float* __restrict__ src = in + (size_t)batch * (NF * LEN);
    const int tid = threadIdx.x;

    // ---- per-field folds ----
    for (int idx = tid; idx < NF * 16; idx += THREADS) {
        const int f = idx >> 4, m = idx & 15;
        const float* x = src + f * LEN;
        const float x0 = x[m], x1 = x[m + 16], x2 = x[m + 32], x3 = x[m + 48];
        const float s = 0.70710678118654752f;
        const float vlo = (x0 - x2) * s, vhi = (x1 - x3) * s;
        const float ulo = x0 + x2,       uhi = x1 + x3;
        const float P = (ulo + uhi) * 0.5f, Q = (ulo - uhi) * 0.5f;
        float* bV = bufV + f * SV;
        bV[m]      = -vlo;  bV[m + 16] = -vhi;
        bV[m + 32] =  vlo;  bV[m + 48] =  vhi;
        float* bP = bufP + f * SP;
        bP[m] = P;  bP[m + 16] = P;
        float* bQ = bufQ + f * SP;
        bQ[m] = -Q; bQ[m + 16] = Q;
    }
    __syncthreads();

    const int role = tid & 1;                          // lanes 2p, 2p+1 share a pair
    int p = blockIdx.y * PAIRS_PER_BLOCK + (tid >> 1);
    const bool live = (tid < ACTIVE);
    if (p >= NPAIR) p = NPAIR - 1;                     // tail threads duplicate, no store
    const int ij = TAB.ij[p];
    const int i  = ij >> 5;
    const int j  = ij & 31;

    // ---- phase 1: negacyclic-32, 16 outputs per role ----
    // QOFF = role*16 folded into B base pointer -> single instantiation,
    // no warp divergence. Role lanes hit banks j / j+16: conflict-free.
    const float* A32 = bufV + i * SV;
    const float* B32 = bufV + j * SV + (role << 4);
    float av[16];
    conv16s<32>(A32, B32, av);                         // av[q] = c2[16*role + q]

    // ---- phase 2: one 16-conv each (role0: cyclic P, role1: negacyclic Q) ----
    const float* A16 = (role ? bufQ : bufP) + i * SP;
    const float* B16 = (role ? bufQ : bufP) + j * SP;
    float d[16];
    conv16s<16>(A16, B16, d);                          // d[q] = d_role[q]

    // ---- fused exchange + reconstruct + store ----
    // role0: c1[q]    = d0[q] + d1[q];  out[q]    = c1+av, out[q+32] = c1-av
    // role1: c1[16+q] = d0[q] - d1[q];  out[16+q] = c1+av, out[q+48] = c1-av
    if (live) {
        const int base = role << 4;  // 0 or 16
        float* __restrict__ dstf = out + ((size_t)batch * NPAIR + p) * LEN + base;
        float4* __restrict__ dst = (float4*)dstf;
#pragma unroll
        for (int g = 0; g < 4; ++g) {
            float rp[4], rm[4];
#pragma unroll
            for (int r = 0; r < 4; ++r) {
                const int q = 4 * g + r;
                const float other = __shfl_xor_sync(0xFFFFFFFFu, d[q], 1);
                const float c1 = role ? (other - d[q]) : (d[q] + other);
                rp[r] = c1 + av[q];
                rm[r] = c1 - av[q];
            }
            dst[g]     = make_float4(rp[0], rp[1], rp[2], rp[3]);
            dst[g + 8] = make_float4(rm[0], rm[1], rm[2], rm[3]);
        }
    } else {
        // keep shuffles convergent for the duplicated tail threads
#pragma unroll
        for (int q = 0; q < 16; ++q)
            (void)__shfl_xor_sync(0xFFFFFFFFu, d[q], 1);
    }
}

extern "C" void kernel_launch(void* const* d_in, const int* in_sizes, int n_in,
                              void* d_out, int out_size)
{
    const float* in  = (const float*)d_in[0];
    float*       out = (float*)d_out;
    const int batches = in_sizes[0] / (NF * LEN);   // 2048 for the bench shape
    dim3 grid(batches, 3);
    holo_r12_kernel<<<grid, THREADS>>>(in, out);
}